// round 3
// baseline (speedup 1.0000x reference)
#include <cuda_runtime.h>
#include <math.h>

#define TSIG (1 << 20)
#define KM 3
#define ALPHA_C 2000.0f
#define TAU_C 1e-7f
#define TAU2F 1e-14f
#define TOL_C 1e-6
#define NITER 50
#define GRID_ITER 888
#define SPITCH 1028
#define SMEM_FFT ((8 * SPITCH + 512) * (int)sizeof(float2))

// Scratch layout in g_buf:
// [0,T)    : F (forward FFT of x)
// [T,2T)   : lam buffer 0
// [2T,3T)  : lam buffer 1
// [3T,6T)  : FFT work (forward pass1 out; inverse pass1 out, 3 modes)
__device__ float2 g_buf[6 * (size_t)TSIG];
__device__ float  g_part[GRID_ITER * 8];
__device__ float  g_omega[2][KM];
__device__ int    g_done;
__device__ int    g_fp;
__device__ unsigned g_counter;

__device__ __forceinline__ float2 cmulf(float2 a, float2 b) {
    return make_float2(a.x * b.x - a.y * b.y, a.x * b.y + a.y * b.x);
}

// ---------------------------------------------------------------------------
// Four-step FFT, N = 1024 x 1024. Stockham radix-2 DIF in shared memory,
// 4 sub-FFTs (columns) per block, 256 threads, shared W_1024 twiddle table.
// All twiddle args are dyadic (m/512, m/2^19) so sincospif reduction is exact.
// ---------------------------------------------------------------------------

__device__ __forceinline__ void fft1024_shared(float2*& src, float2*& dst,
                                               const float2* tw, int t) {
    #pragma unroll 1
    for (int s = 0; s < 10; s++) {
        int r = 1 << s;
        #pragma unroll
        for (int u = 0; u < 8; u++) {
            int id = u * 256 + t;          // 0..2047
            int c  = id >> 9;              // column 0..3
            int bf = id & 511;             // butterfly 0..511
            int j  = bf >> s;
            float2 a = src[c * SPITCH + bf];
            float2 b = src[c * SPITCH + bf + 512];
            float2 w = tw[j << s];
            int o = bf + ((bf >> s) << s);
            dst[c * SPITCH + o]     = make_float2(a.x + b.x, a.y + b.y);
            float2 d = make_float2(a.x - b.x, a.y - b.y);
            dst[c * SPITCH + o + r] = cmulf(d, w);
        }
        __syncthreads();
        float2* tmp = src; src = dst; dst = tmp;
    }
}

__device__ __forceinline__ void build_tw(float2* tw, int t) {
    for (int m = t; m < 512; m += 256) {
        float s, c;
        sincospif((float)m * (1.0f / 512.0f), &s, &c);  // exp(-2pi i m/1024)
        tw[m] = make_float2(c, -s);
    }
}

// MODE 0: real input x.  MODE 1: fused u_hat from (F, lam, omega), conjugated
// for the ifft-via-fft trick; blockIdx.y = mode index.
template <int MODE>
__global__ void __launch_bounds__(256) fft_pass1(const float* rin, float2* out) {
    extern __shared__ float2 sh[];
    float2* bufA = sh;
    float2* bufB = sh + 4 * SPITCH;
    float2* tw   = sh + 8 * SPITCH;
    const int t   = threadIdx.x;
    const int n2b = blockIdx.x * 4;
    const int b   = blockIdx.y;

    build_tw(tw, t);

    float w0 = 0.f, w1 = 0.f, w2 = 0.f;
    const float2* __restrict__ F   = g_buf;
    const float2* __restrict__ lam = g_buf;
    if (MODE == 1) {
        int fp = g_fp;
        w0 = g_omega[fp][0]; w1 = g_omega[fp][1]; w2 = g_omega[fp][2];
        lam = g_buf + (size_t)TSIG * (1 + fp);
    }
    const float invT = 1.0f / (float)TSIG;

    for (int i = t; i < 4096; i += 256) {
        int n1 = i >> 2, c = i & 3;
        int j = (n1 << 10) + n2b + c;
        float2 v;
        if (MODE == 0) {
            v = make_float2(rin[j], 0.0f);
        } else {
            float f = (float)j * invT;
            if (j >= TSIG / 2) f -= 1.0f;
            float2 Fv = F[j];
            float2 Lv = lam[j];
            float rr = Fv.x - 0.5f * Lv.x;
            float ri = Fv.y - 0.5f * Lv.y;
            float d0 = f - w0, d1 = f - w1, d2 = f - w2;
            float b0 = d0 * d0, b1 = d1 * d1, b2 = d2 * d2;
            float sum = (b == 0) ? (b0 + b1) : (b == 1) ? (b0 + b1 + b2) : (b1 + b2);
            float iv = __fdividef(1.0f, fmaf(ALPHA_C, sum + TAU2F, 1.0f));
            v = make_float2(rr * iv, -(ri * iv));   // conj(u_hat)
        }
        bufA[c * SPITCH + n1] = v;
    }
    __syncthreads();

    float2 *src = bufA, *dst = bufB;
    fft1024_shared(src, dst, tw, t);

    // multiply by W_N^(n2*k1), store A[k1*1024 + n2]
    for (int i = t; i < 4096; i += 256) {
        int k1 = i >> 2, c = i & 3;
        int n2 = n2b + c;
        int m = n2 * k1;                           // < 2^20, exact in float
        float s, cth;
        sincospif((float)m * (1.0f / 524288.0f), &s, &cth);
        float2 v = src[c * SPITCH + k1];
        out[(size_t)b * TSIG + ((size_t)k1 << 10) + n2] =
            cmulf(v, make_float2(cth, -s));
    }
}

template <int REAL_OUT>
__global__ void __launch_bounds__(256) fft_pass2(const float2* in, float2* cout,
                                                 float* rout) {
    extern __shared__ float2 sh[];
    float2* bufA = sh;
    float2* bufB = sh + 4 * SPITCH;
    float2* tw   = sh + 8 * SPITCH;
    const int t   = threadIdx.x;
    const int k1b = blockIdx.x * 4;
    const int b   = blockIdx.y;

    build_tw(tw, t);
    for (int i = t; i < 4096; i += 256) {
        int c = i >> 10, n2 = i & 1023;
        bufA[c * SPITCH + n2] = in[(size_t)b * TSIG + ((size_t)(k1b + c) << 10) + n2];
    }
    __syncthreads();

    float2 *src = bufA, *dst = bufB;
    fft1024_shared(src, dst, tw, t);

    const float invT = 1.0f / (float)TSIG;
    for (int i = t; i < 4096; i += 256) {
        int k2 = i >> 2, c = i & 3;
        float2 v = src[c * SPITCH + k2];
        size_t o = (size_t)b * TSIG + ((size_t)k2 << 10) + k1b + c;
        if (REAL_OUT) rout[o] = v.x * invT;
        else          cout[o] = v;
    }
}

// ---------------------------------------------------------------------------
// VMD iteration (fused finalize via last-block ticket)
// ---------------------------------------------------------------------------

__global__ void vmd_init(const float* om_init) {
    int idx = blockIdx.x * blockDim.x + threadIdx.x;
    if (idx < KM) g_omega[0][idx] = om_init[idx];
    if (idx == 0) { g_done = 0; g_fp = 1; g_counter = 0; }
    int stride = gridDim.x * blockDim.x;
    for (int j = idx; j < TSIG; j += stride)
        g_buf[(size_t)TSIG + j] = make_float2(0.0f, 0.0f);
}

// Reciprocal-batched denominators: i_k = 1/(1 + alpha*denom_k)
__device__ __forceinline__ void inv3(float b0, float b1, float b2,
                                     float& i0, float& i1, float& i2) {
    float a = fmaf(ALPHA_C, b0 + b1 + TAU2F, 1.0f);
    float b = fmaf(ALPHA_C, b2, a);
    float c = fmaf(ALPHA_C, b1 + b2 + TAU2F, 1.0f);
    float inv = __fdividef(1.0f, a * b * c);
    i0 = inv * (b * c);
    i1 = inv * (a * c);
    i2 = inv * (a * b);
}

template <int DO_CHECK>
__global__ void __launch_bounds__(256, 6) vmd_iter(int n) {
    if (g_done) return;
    const int pi = n & 1, po = pi ^ 1;
    const float4* __restrict__ F4 = reinterpret_cast<const float4*>(g_buf);
    const float4* __restrict__ Li4 =
        reinterpret_cast<const float4*>(g_buf + (size_t)TSIG * (1 + pi));
    float4* __restrict__ Lo4 =
        reinterpret_cast<float4*>(g_buf + (size_t)TSIG * (1 + po));
    const float w0 = g_omega[pi][0], w1 = g_omega[pi][1], w2 = g_omega[pi][2];
    float p0 = 0.f, p1 = 0.f, p2 = 0.f;
    if (DO_CHECK) { p0 = g_omega[po][0]; p1 = g_omega[po][1]; p2 = g_omega[po][2]; }

    float acc[8] = {0, 0, 0, 0, 0, 0, 0, 0};
    const float invT = 1.0f / (float)TSIG;
    const int NP = TSIG / 2;
    int tid = blockIdx.x * blockDim.x + threadIdx.x;
    int stride = gridDim.x * blockDim.x;

    for (int p = tid; p < NP; p += stride) {
        int j0 = p << 1;
        float f0 = (float)j0 * invT;
        if (j0 >= TSIG / 2) f0 -= 1.0f;          // pair never straddles the wrap
        float f1 = f0 + invT;
        float4 Fv = F4[p];
        float4 Lv = Li4[p];
        float4 Lold;
        if (DO_CHECK) Lold = Lo4[p];             // L_{n-1}: read before overwrite
        float4 Lout;

        #pragma unroll
        for (int e = 0; e < 2; e++) {
            float f  = e ? f1 : f0;
            float Fr = e ? Fv.z : Fv.x,  Fi = e ? Fv.w : Fv.y;
            float Lr = e ? Lv.z : Lv.x,  Li = e ? Lv.w : Lv.y;
            float rr = Fr - 0.5f * Lr;
            float ri = Fi - 0.5f * Li;
            float d0 = f - w0, d1 = f - w1, d2 = f - w2;
            float i0, i1, i2;
            inv3(d0 * d0, d1 * d1, d2 * d2, i0, i1, i2);
            float mag = rr * rr + ri * ri;
            float pw0 = mag * i0 * i0, pw1 = mag * i1 * i1, pw2 = mag * i2 * i2;
            acc[0] += pw0; acc[1] += pw1; acc[2] += pw2;
            acc[3] += f * pw0; acc[4] += f * pw1; acc[5] += f * pw2;
            float isum = i0 + i1 + i2;
            float lr = Lr + TAU_C * (rr * isum - Fr);
            float li = Li + TAU_C * (ri * isum - Fi);
            if (e) { Lout.z = lr; Lout.w = li; } else { Lout.x = lr; Lout.y = li; }

            if (DO_CHECK) {
                float qr = (e ? Fv.z : Fv.x) - 0.5f * (e ? Lold.z : Lold.x);
                float qi = (e ? Fv.w : Fv.y) - 0.5f * (e ? Lold.w : Lold.y);
                float e0 = f - p0, e1 = f - p1, e2 = f - p2;
                float h0, h1, h2;
                inv3(e0 * e0, e1 * e1, e2 * e2, h0, h1, h2);
                float qmag = qr * qr + qi * qi;
                acc[7] += qmag * (h0 * h0 + h1 * h1 + h2 * h2);
                float xr, xi;
                xr = rr * i0 - qr * h0; xi = ri * i0 - qi * h0; acc[6] += xr * xr + xi * xi;
                xr = rr * i1 - qr * h1; xi = ri * i1 - qi * h1; acc[6] += xr * xr + xi * xi;
                xr = rr * i2 - qr * h2; xi = ri * i2 - qi * h2; acc[6] += xr * xr + xi * xi;
            }
        }
        Lo4[p] = Lout;
    }

    // block reduction of 8 partials
    __shared__ float sred[8][8];
    int lane = threadIdx.x & 31, warp = threadIdx.x >> 5;
    #pragma unroll
    for (int a = 0; a < 8; a++) {
        float v = acc[a];
        #pragma unroll
        for (int o = 16; o; o >>= 1) v += __shfl_down_sync(0xffffffffu, v, o);
        if (lane == 0) sred[warp][a] = v;
    }
    __syncthreads();
    if (threadIdx.x < 8) {
        int a = threadIdx.x;
        float s = 0;
        #pragma unroll
        for (int w = 0; w < 8; w++) s += sred[w][a];
        g_part[blockIdx.x * 8 + a] = s;
    }

    // last-block fused finalize
    __shared__ bool amLast;
    if (threadIdx.x == 0) {
        __threadfence();
        unsigned t = atomicInc(&g_counter, gridDim.x - 1);  // auto-reset at wrap
        amLast = (t == gridDim.x - 1);
    }
    __syncthreads();
    if (!amLast) return;
    __threadfence();

    double loc[8] = {0, 0, 0, 0, 0, 0, 0, 0};
    for (int bidx = threadIdx.x; bidx < GRID_ITER; bidx += 256) {
        #pragma unroll
        for (int a = 0; a < 8; a++) loc[a] += (double)g_part[bidx * 8 + a];
    }
    __shared__ double dred[8][8];
    #pragma unroll
    for (int a = 0; a < 8; a++) {
        double v = loc[a];
        #pragma unroll
        for (int o = 16; o; o >>= 1) v += __shfl_down_sync(0xffffffffu, v, o);
        if (lane == 0) dred[warp][a] = v;
    }
    __syncthreads();
    if (threadIdx.x == 0) {
        double s[8];
        #pragma unroll
        for (int a = 0; a < 8; a++) {
            double v = 0;
            for (int w = 0; w < 8; w++) v += dred[w][a];
            s[a] = v;
        }
        double wn0 = s[3] / s[0], wn1 = s[4] / s[1], wn2 = s[5] / s[2];
        g_omega[po][0] = (float)wn0;
        g_omega[po][1] = (float)wn1;
        g_omega[po][2] = (float)wn2;
        if (DO_CHECK) {
            double udiff = s[6] / s[7];
            double omd = (fabs(wn0 - wn2) + fabs(wn1 - wn0) + fabs(wn2 - wn1)) * (1.0 / 3.0);
            if (udiff < TOL_C && omd < TOL_C) { g_done = 1; g_fp = n & 1; }
        }
    }
}

// ---------------------------------------------------------------------------

extern "C" void kernel_launch(void* const* d_in, const int* in_sizes, int n_in,
                              void* d_out, int out_size) {
    const float* x       = (const float*)d_in[0];
    const float* om_init = (const float*)d_in[1];
    float* out = (float*)d_out;

    cudaFuncSetAttribute(fft_pass1<0>, cudaFuncAttributeMaxDynamicSharedMemorySize, SMEM_FFT);
    cudaFuncSetAttribute(fft_pass1<1>, cudaFuncAttributeMaxDynamicSharedMemorySize, SMEM_FFT);
    cudaFuncSetAttribute(fft_pass2<0>, cudaFuncAttributeMaxDynamicSharedMemorySize, SMEM_FFT);
    cudaFuncSetAttribute(fft_pass2<1>, cudaFuncAttributeMaxDynamicSharedMemorySize, SMEM_FFT);

    float2* buf;
    cudaGetSymbolAddress((void**)&buf, g_buf);
    float2* F  = buf;                       // [0, T)
    float2* wk = buf + (size_t)3 * TSIG;    // FFT work region (3T)

    // Forward FFT of x -> F
    fft_pass1<0><<<dim3(256, 1), 256, SMEM_FFT>>>(x, wk);
    fft_pass2<0><<<dim3(256, 1), 256, SMEM_FFT>>>(wk, F, nullptr);

    vmd_init<<<512, 256>>>(om_init);

    for (int n = 0; n < NITER; n++) {
        if (n % 10 == 0 && n > 0) vmd_iter<1><<<GRID_ITER, 256>>>(n);
        else                      vmd_iter<0><<<GRID_ITER, 256>>>(n);
    }

    // inverse: pass1 computes conj(u_hat) on the fly (F, lam, omega still live),
    // then Re(fft(conj(u)))/T
    fft_pass1<1><<<dim3(256, 3), 256, SMEM_FFT>>>(nullptr, wk);
    fft_pass2<1><<<dim3(256, 3), 256, SMEM_FFT>>>(wk, nullptr, out);
}

// round 4
// speedup vs baseline: 1.3980x; 1.3980x over previous
#include <cuda_runtime.h>
#include <math.h>

#define TSIG (1 << 20)
#define KM 3
#define ALPHA_C 2000.0f
#define TAU_C 1e-7f
#define TAU2F 1e-14f
#define TOL_C 1e-6
#define NITER 50
#define MAXGRID 2048
#define SPITCH 1028
#define SMEM_FFT ((8 * SPITCH + 512) * (int)sizeof(float2))

// Scratch layout in g_buf:
// [0,T)    : F (forward FFT of x)
// [T,2T)   : lam buffer 0
// [2T,3T)  : lam buffer 1
// [3T,6T)  : FFT work (forward pass1 out; inverse pass1 out, 3 modes)
__device__ float2 g_buf[6 * (size_t)TSIG];
__device__ float  g_part[MAXGRID * 8];
__device__ float  g_omega[2][KM];
__device__ int    g_done;
__device__ int    g_fp;
__device__ unsigned g_bar_count;
__device__ volatile unsigned g_bar_gen;

__device__ __forceinline__ float2 cmulf(float2 a, float2 b) {
    return make_float2(a.x * b.x - a.y * b.y, a.x * b.y + a.y * b.x);
}

// ---------------------------------------------------------------------------
// Four-step FFT, N = 1024 x 1024. Stockham radix-2 DIF in shared memory,
// 4 sub-FFTs (columns) per block, 256 threads, shared W_1024 twiddle table.
// All twiddle args are dyadic (m/512, m/2^19) so sincospif reduction is exact.
// ---------------------------------------------------------------------------

__device__ __forceinline__ void fft1024_shared(float2*& src, float2*& dst,
                                               const float2* tw, int t) {
    #pragma unroll 1
    for (int s = 0; s < 10; s++) {
        int r = 1 << s;
        #pragma unroll
        for (int u = 0; u < 8; u++) {
            int id = u * 256 + t;          // 0..2047
            int c  = id >> 9;              // column 0..3
            int bf = id & 511;             // butterfly 0..511
            int j  = bf >> s;
            float2 a = src[c * SPITCH + bf];
            float2 b = src[c * SPITCH + bf + 512];
            float2 w = tw[j << s];
            int o = bf + ((bf >> s) << s);
            dst[c * SPITCH + o]     = make_float2(a.x + b.x, a.y + b.y);
            float2 d = make_float2(a.x - b.x, a.y - b.y);
            dst[c * SPITCH + o + r] = cmulf(d, w);
        }
        __syncthreads();
        float2* tmp = src; src = dst; dst = tmp;
    }
}

__device__ __forceinline__ void build_tw(float2* tw, int t) {
    for (int m = t; m < 512; m += 256) {
        float s, c;
        sincospif((float)m * (1.0f / 512.0f), &s, &c);  // exp(-2pi i m/1024)
        tw[m] = make_float2(c, -s);
    }
}

// MODE 0: real input x.  MODE 1: fused u_hat from (F, lam, omega), conjugated
// for the ifft-via-fft trick; blockIdx.y = mode index.
template <int MODE>
__global__ void __launch_bounds__(256) fft_pass1(const float* rin, float2* out) {
    extern __shared__ float2 sh[];
    float2* bufA = sh;
    float2* bufB = sh + 4 * SPITCH;
    float2* tw   = sh + 8 * SPITCH;
    const int t   = threadIdx.x;
    const int n2b = blockIdx.x * 4;
    const int b   = blockIdx.y;

    build_tw(tw, t);

    float w0 = 0.f, w1 = 0.f, w2 = 0.f;
    const float2* __restrict__ F   = g_buf;
    const float2* __restrict__ lam = g_buf;
    if (MODE == 1) {
        int fp = g_fp;
        w0 = g_omega[fp][0]; w1 = g_omega[fp][1]; w2 = g_omega[fp][2];
        lam = g_buf + (size_t)TSIG * (1 + fp);
    }
    const float invT = 1.0f / (float)TSIG;

    for (int i = t; i < 4096; i += 256) {
        int n1 = i >> 2, c = i & 3;
        int j = (n1 << 10) + n2b + c;
        float2 v;
        if (MODE == 0) {
            v = make_float2(rin[j], 0.0f);
        } else {
            float f = (float)j * invT;
            if (j >= TSIG / 2) f -= 1.0f;
            float2 Fv = F[j];
            float2 Lv = lam[j];
            float rr = Fv.x - 0.5f * Lv.x;
            float ri = Fv.y - 0.5f * Lv.y;
            float d0 = f - w0, d1 = f - w1, d2 = f - w2;
            float b0 = d0 * d0, b1 = d1 * d1, b2 = d2 * d2;
            float sum = (b == 0) ? (b0 + b1) : (b == 1) ? (b0 + b1 + b2) : (b1 + b2);
            float iv = __fdividef(1.0f, fmaf(ALPHA_C, sum + TAU2F, 1.0f));
            v = make_float2(rr * iv, -(ri * iv));   // conj(u_hat)
        }
        bufA[c * SPITCH + n1] = v;
    }
    __syncthreads();

    float2 *src = bufA, *dst = bufB;
    fft1024_shared(src, dst, tw, t);

    // multiply by W_N^(n2*k1), store A[k1*1024 + n2]
    for (int i = t; i < 4096; i += 256) {
        int k1 = i >> 2, c = i & 3;
        int n2 = n2b + c;
        int m = n2 * k1;                           // < 2^20, exact in float
        float s, cth;
        sincospif((float)m * (1.0f / 524288.0f), &s, &cth);
        float2 v = src[c * SPITCH + k1];
        out[(size_t)b * TSIG + ((size_t)k1 << 10) + n2] =
            cmulf(v, make_float2(cth, -s));
    }
}

template <int REAL_OUT>
__global__ void __launch_bounds__(256) fft_pass2(const float2* in, float2* cout,
                                                 float* rout) {
    extern __shared__ float2 sh[];
    float2* bufA = sh;
    float2* bufB = sh + 4 * SPITCH;
    float2* tw   = sh + 8 * SPITCH;
    const int t   = threadIdx.x;
    const int k1b = blockIdx.x * 4;
    const int b   = blockIdx.y;

    build_tw(tw, t);
    for (int i = t; i < 4096; i += 256) {
        int c = i >> 10, n2 = i & 1023;
        bufA[c * SPITCH + n2] = in[(size_t)b * TSIG + ((size_t)(k1b + c) << 10) + n2];
    }
    __syncthreads();

    float2 *src = bufA, *dst = bufB;
    fft1024_shared(src, dst, tw, t);

    const float invT = 1.0f / (float)TSIG;
    for (int i = t; i < 4096; i += 256) {
        int k2 = i >> 2, c = i & 3;
        float2 v = src[c * SPITCH + k2];
        size_t o = (size_t)b * TSIG + ((size_t)k2 << 10) + k1b + c;
        if (REAL_OUT) rout[o] = v.x * invT;
        else          cout[o] = v;
    }
}

// ---------------------------------------------------------------------------
// Persistent VMD iteration kernel: all 50 iterations in one launch.
// Grid sized by the host to occupancy*SMs => all blocks co-resident, so a
// software grid barrier (atomic ticket + generation counter) is safe.
// ---------------------------------------------------------------------------

__global__ void vmd_init(const float* om_init) {
    int idx = blockIdx.x * blockDim.x + threadIdx.x;
    if (idx < KM) g_omega[0][idx] = om_init[idx];
    if (idx == 0) { g_done = 0; g_fp = 1; g_bar_count = 0; g_bar_gen = 0; }
    int stride = gridDim.x * blockDim.x;
    for (int j = idx; j < TSIG; j += stride)
        g_buf[(size_t)TSIG + j] = make_float2(0.0f, 0.0f);
}

// Reciprocal-batched denominators: i_k = 1/(1 + alpha*denom_k)
__device__ __forceinline__ void inv3(float b0, float b1, float b2,
                                     float& i0, float& i1, float& i2) {
    float a = fmaf(ALPHA_C, b0 + b1 + TAU2F, 1.0f);
    float b = fmaf(ALPHA_C, b2, a);
    float c = fmaf(ALPHA_C, b1 + b2 + TAU2F, 1.0f);
    float inv = __fdividef(1.0f, a * b * c);
    i0 = inv * (b * c);
    i1 = inv * (a * c);
    i2 = inv * (a * b);
}

__global__ void __launch_bounds__(256) vmd_persist() {
    const int tix = threadIdx.x;
    const int lane = tix & 31, warp = tix >> 5;
    const int nblk = gridDim.x;
    const float invT = 1.0f / (float)TSIG;
    const int NP = TSIG / 2;
    const int tid = blockIdx.x * 256 + tix;
    const int stride = nblk * 256;

    __shared__ bool amLast;
    __shared__ float sred[8][8];
    __shared__ double dred[8][8];

    for (int n = 0; n < NITER; n++) {
        const int pi = n & 1, po = pi ^ 1;
        const int do_check = (n % 10 == 0 && n > 0);
        const volatile float* om = &g_omega[0][0];
        const float w0 = om[pi * KM + 0], w1 = om[pi * KM + 1], w2 = om[pi * KM + 2];
        float p0 = 0.f, p1 = 0.f, p2 = 0.f;
        if (do_check) { p0 = om[po * KM + 0]; p1 = om[po * KM + 1]; p2 = om[po * KM + 2]; }

        const float4* __restrict__ F4 = reinterpret_cast<const float4*>(g_buf);
        const float4* __restrict__ Li4 =
            reinterpret_cast<const float4*>(g_buf + (size_t)TSIG * (1 + pi));
        float4* __restrict__ Lo4 =
            reinterpret_cast<float4*>(g_buf + (size_t)TSIG * (1 + po));

        float acc[8] = {0, 0, 0, 0, 0, 0, 0, 0};

        for (int p = tid; p < NP; p += stride) {
            int j0 = p << 1;
            float f0 = (float)j0 * invT;
            if (j0 >= TSIG / 2) f0 -= 1.0f;      // pair never straddles the wrap
            float f1 = f0 + invT;
            float4 Fv = F4[p];
            float4 Lv = Li4[p];
            float4 Lold;
            if (do_check) Lold = Lo4[p];         // L_{n-1}: read before overwrite
            float4 Lout;

            #pragma unroll
            for (int e = 0; e < 2; e++) {
                float f  = e ? f1 : f0;
                float Fr = e ? Fv.z : Fv.x,  Fi = e ? Fv.w : Fv.y;
                float Lr = e ? Lv.z : Lv.x,  Li = e ? Lv.w : Lv.y;
                float rr = Fr - 0.5f * Lr;
                float ri = Fi - 0.5f * Li;
                float d0 = f - w0, d1 = f - w1, d2 = f - w2;
                float i0, i1, i2;
                inv3(d0 * d0, d1 * d1, d2 * d2, i0, i1, i2);
                float mag = rr * rr + ri * ri;
                float pw0 = mag * i0 * i0, pw1 = mag * i1 * i1, pw2 = mag * i2 * i2;
                acc[0] += pw0; acc[1] += pw1; acc[2] += pw2;
                acc[3] += f * pw0; acc[4] += f * pw1; acc[5] += f * pw2;
                float isum = i0 + i1 + i2;
                float lr = Lr + TAU_C * (rr * isum - Fr);
                float li = Li + TAU_C * (ri * isum - Fi);
                if (e) { Lout.z = lr; Lout.w = li; } else { Lout.x = lr; Lout.y = li; }

                if (do_check) {
                    float qr = (e ? Fv.z : Fv.x) - 0.5f * (e ? Lold.z : Lold.x);
                    float qi = (e ? Fv.w : Fv.y) - 0.5f * (e ? Lold.w : Lold.y);
                    float e0 = f - p0, e1 = f - p1, e2 = f - p2;
                    float h0, h1, h2;
                    inv3(e0 * e0, e1 * e1, e2 * e2, h0, h1, h2);
                    float qmag = qr * qr + qi * qi;
                    acc[7] += qmag * (h0 * h0 + h1 * h1 + h2 * h2);
                    float xr, xi;
                    xr = rr * i0 - qr * h0; xi = ri * i0 - qi * h0; acc[6] += xr * xr + xi * xi;
                    xr = rr * i1 - qr * h1; xi = ri * i1 - qi * h1; acc[6] += xr * xr + xi * xi;
                    xr = rr * i2 - qr * h2; xi = ri * i2 - qi * h2; acc[6] += xr * xr + xi * xi;
                }
            }
            Lo4[p] = Lout;
        }

        // block reduction of 8 partials -> g_part[block]
        #pragma unroll
        for (int a = 0; a < 8; a++) {
            float v = acc[a];
            #pragma unroll
            for (int o = 16; o; o >>= 1) v += __shfl_down_sync(0xffffffffu, v, o);
            if (lane == 0) sred[warp][a] = v;
        }
        __syncthreads();
        if (tix < 8) {
            int a = tix;
            float s = 0;
            #pragma unroll
            for (int w = 0; w < 8; w++) s += sred[w][a];
            g_part[blockIdx.x * 8 + a] = s;
        }
        __syncthreads();

        // grid barrier: ticket; last block finalizes and releases generation
        if (tix == 0) {
            __threadfence();
            unsigned t = atomicAdd(&g_bar_count, 1u);
            amLast = (t == (unsigned)nblk - 1);
        }
        __syncthreads();

        if (amLast) {
            __threadfence();
            double loc[8] = {0, 0, 0, 0, 0, 0, 0, 0};
            for (int b = tix; b < nblk; b += 256) {
                #pragma unroll
                for (int a = 0; a < 8; a++) loc[a] += (double)g_part[b * 8 + a];
            }
            #pragma unroll
            for (int a = 0; a < 8; a++) {
                double v = loc[a];
                #pragma unroll
                for (int o = 16; o; o >>= 1) v += __shfl_down_sync(0xffffffffu, v, o);
                if (lane == 0) dred[warp][a] = v;
            }
            __syncthreads();
            if (tix == 0) {
                double s[8];
                #pragma unroll
                for (int a = 0; a < 8; a++) {
                    double v = 0;
                    for (int w = 0; w < 8; w++) v += dred[w][a];
                    s[a] = v;
                }
                double wn0 = s[3] / s[0], wn1 = s[4] / s[1], wn2 = s[5] / s[2];
                g_omega[po][0] = (float)wn0;
                g_omega[po][1] = (float)wn1;
                g_omega[po][2] = (float)wn2;
                if (do_check) {
                    double udiff = s[6] / s[7];
                    double omd = (fabs(wn0 - wn2) + fabs(wn1 - wn0) + fabs(wn2 - wn1)) * (1.0 / 3.0);
                    if (udiff < TOL_C && omd < TOL_C) { g_done = 1; g_fp = n & 1; }
                }
                g_bar_count = 0;
                __threadfence();
                g_bar_gen = (unsigned)(n + 1);   // release
            }
            __syncthreads();
        } else {
            if (tix == 0) {
                while (g_bar_gen < (unsigned)(n + 1)) __nanosleep(128);
            }
            __syncthreads();
        }
        __threadfence();                          // acquire for omega/done
        if (*(volatile int*)&g_done) break;
    }
}

// ---------------------------------------------------------------------------

extern "C" void kernel_launch(void* const* d_in, const int* in_sizes, int n_in,
                              void* d_out, int out_size) {
    const float* x       = (const float*)d_in[0];
    const float* om_init = (const float*)d_in[1];
    float* out = (float*)d_out;

    cudaFuncSetAttribute(fft_pass1<0>, cudaFuncAttributeMaxDynamicSharedMemorySize, SMEM_FFT);
    cudaFuncSetAttribute(fft_pass1<1>, cudaFuncAttributeMaxDynamicSharedMemorySize, SMEM_FFT);
    cudaFuncSetAttribute(fft_pass2<0>, cudaFuncAttributeMaxDynamicSharedMemorySize, SMEM_FFT);
    cudaFuncSetAttribute(fft_pass2<1>, cudaFuncAttributeMaxDynamicSharedMemorySize, SMEM_FFT);

    // co-residency-safe persistent grid
    int occ = 0, sms = 0, dev = 0;
    cudaOccupancyMaxActiveBlocksPerMultiprocessor(&occ, vmd_persist, 256, 0);
    cudaGetDevice(&dev);
    cudaDeviceGetAttribute(&sms, cudaDevAttrMultiProcessorCount, dev);
    if (occ < 1) occ = 1;
    int grid = occ * sms;
    if (grid > MAXGRID) grid = MAXGRID;
    if (grid < 1) grid = 1;

    float2* buf;
    cudaGetSymbolAddress((void**)&buf, g_buf);
    float2* F  = buf;                       // [0, T)
    float2* wk = buf + (size_t)3 * TSIG;    // FFT work region (3T)

    // Forward FFT of x -> F
    fft_pass1<0><<<dim3(256, 1), 256, SMEM_FFT>>>(x, wk);
    fft_pass2<0><<<dim3(256, 1), 256, SMEM_FFT>>>(wk, F, nullptr);

    vmd_init<<<512, 256>>>(om_init);

    vmd_persist<<<grid, 256>>>();

    // inverse: pass1 computes conj(u_hat) on the fly (F, lam, omega still live),
    // then Re(fft(conj(u)))/T
    fft_pass1<1><<<dim3(256, 3), 256, SMEM_FFT>>>(nullptr, wk);
    fft_pass2<1><<<dim3(256, 3), 256, SMEM_FFT>>>(wk, nullptr, out);
}